// round 1
// baseline (speedup 1.0000x reference)
#include <cuda_runtime.h>
#include <cuda_bf16.h>
#include <math_constants.h>

// Problem constants
#define B_SZ   4
#define T_SEQ  2048
#define C_EMB  1024
#define NH     16
#define HS     64
#define C3     (3 * C_EMB)           // 3072
#define MROWS  (B_SZ * T_SEQ)        // 8192

// Scratch (device globals -- no allocation allowed)
__device__ float g_qkv[(size_t)MROWS * C3];     // [8192, 3072]  q|k|v
__device__ float g_att[(size_t)MROWS * C_EMB];  // [8192, 1024]  attention output (head-interleaved = final y layout)

// ---------------------------------------------------------------------------
// GEMM: C[M,N] = A[M,K] * B[N,K]^T   (both row-major, K contiguous)
// Tile 128x128x16, 256 threads, 8x8 per thread.
// Requires M%128==0, N%128==0, K%16==0 (true for all our shapes).
// ---------------------------------------------------------------------------
__global__ __launch_bounds__(256) void gemm_nt_kernel(
    const float* __restrict__ A, const float* __restrict__ B,
    float* __restrict__ C, int M, int N, int K)
{
    __shared__ float As[16][128];
    __shared__ float Bs[16][128];

    const int tid = threadIdx.x;
    const int bm = blockIdx.y * 128;
    const int bn = blockIdx.x * 128;
    const int ty = tid >> 4;        // 0..15
    const int tx = tid & 15;        // 0..15

    const int lr = tid >> 2;        // 0..63 (loader row within half-tile)
    const int lk = (tid & 3) << 2;  // 0,4,8,12 (k offset)

    const float* Aptr = A + (size_t)(bm + lr) * K + lk;
    const float* Bptr = B + (size_t)(bn + lr) * K + lk;
    const size_t strideA = (size_t)64 * K;

    float acc[8][8];
#pragma unroll
    for (int i = 0; i < 8; i++)
#pragma unroll
        for (int j = 0; j < 8; j++) acc[i][j] = 0.0f;

    for (int k0 = 0; k0 < K; k0 += 16) {
        float4 a0 = *(const float4*)(Aptr + k0);
        float4 a1 = *(const float4*)(Aptr + strideA + k0);
        float4 b0 = *(const float4*)(Bptr + k0);
        float4 b1 = *(const float4*)(Bptr + strideA + k0);

        __syncthreads();  // previous iteration's reads complete

        As[lk + 0][lr]      = a0.x; As[lk + 1][lr]      = a0.y;
        As[lk + 2][lr]      = a0.z; As[lk + 3][lr]      = a0.w;
        As[lk + 0][lr + 64] = a1.x; As[lk + 1][lr + 64] = a1.y;
        As[lk + 2][lr + 64] = a1.z; As[lk + 3][lr + 64] = a1.w;

        Bs[lk + 0][lr]      = b0.x; Bs[lk + 1][lr]      = b0.y;
        Bs[lk + 2][lr]      = b0.z; Bs[lk + 3][lr]      = b0.w;
        Bs[lk + 0][lr + 64] = b1.x; Bs[lk + 1][lr + 64] = b1.y;
        Bs[lk + 2][lr + 64] = b1.z; Bs[lk + 3][lr + 64] = b1.w;

        __syncthreads();

#pragma unroll
        for (int k = 0; k < 16; k++) {
            float4 afa = *(const float4*)&As[k][ty * 8];
            float4 afb = *(const float4*)&As[k][ty * 8 + 4];
            float4 bfa = *(const float4*)&Bs[k][tx * 8];
            float4 bfb = *(const float4*)&Bs[k][tx * 8 + 4];
            float af[8] = {afa.x, afa.y, afa.z, afa.w, afb.x, afb.y, afb.z, afb.w};
            float bf[8] = {bfa.x, bfa.y, bfa.z, bfa.w, bfb.x, bfb.y, bfb.z, bfb.w};
#pragma unroll
            for (int i = 0; i < 8; i++)
#pragma unroll
                for (int j = 0; j < 8; j++)
                    acc[i][j] = fmaf(af[i], bf[j], acc[i][j]);
        }
    }

#pragma unroll
    for (int i = 0; i < 8; i++) {
        float* Crow = C + (size_t)(bm + ty * 8 + i) * N + bn + tx * 8;
        *(float4*)(Crow)     = make_float4(acc[i][0], acc[i][1], acc[i][2], acc[i][3]);
        *(float4*)(Crow + 4) = make_float4(acc[i][4], acc[i][5], acc[i][6], acc[i][7]);
    }
}

// ---------------------------------------------------------------------------
// Flash attention, causal. One block = (b, h, 64-query tile).
// 256 threads as 16x16; each thread owns a 4x4 patch of the 64x64 score tile
// and a 4x4 patch of the 64(q) x 64(hs) output tile.
// Shared: Qs [64x64], Kt/Ps aliased [64x64], Vs [64x64] = 48 KB static.
// Output written head-interleaved into g_att = final y layout [B,T,C].
// ---------------------------------------------------------------------------
__global__ __launch_bounds__(256) void flash_attn_kernel(
    const float* __restrict__ qkv, float* __restrict__ y)
{
    __shared__ float Qs[64 * 64];
    __shared__ float KP[64 * 64];   // K^T (d-major) during S; P during PV
    __shared__ float Vs[64 * 64];

    const int qt = blockIdx.x;                 // 0..31
    const int h  = blockIdx.y;                 // 0..15
    const int b  = blockIdx.z;                 // 0..3
    const int tid = threadIdx.x;
    const int ty = tid >> 4;                   // 0..15
    const int tx = tid & 15;                   // 0..15
    const int q0 = qt * 64;

    // qkv[(b*T + t)*3C + section + h*HS + d]
    const size_t rowbase = (size_t)b * T_SEQ;
    const size_t qoff = (size_t)h * HS;                 // q section
    const size_t koff = (size_t)C_EMB + h * HS;         // k section
    const size_t voff = (size_t)2 * C_EMB + h * HS;     // v section

    const int lr  = tid >> 2;             // 0..63 loader row
    const int lc0 = (tid & 3) * 4;        // 0,4,8,12 -> cols lc0 + p*16

    // ---- load Q tile: Qs[r][d] ----
#pragma unroll
    for (int p = 0; p < 4; p++) {
        int c = lc0 + p * 16;
        float4 v = *(const float4*)(qkv + (rowbase + q0 + lr) * C3 + qoff + c);
        *(float4*)&Qs[lr * 64 + c] = v;
    }

    float m_run[4], l_run[4], O[4][4];
#pragma unroll
    for (int i = 0; i < 4; i++) {
        m_run[i] = -CUDART_INF_F;
        l_run[i] = 0.0f;
#pragma unroll
        for (int j = 0; j < 4; j++) O[i][j] = 0.0f;
    }

    for (int kt = 0; kt <= qt; kt++) {
        const int kv0 = kt * 64;

        __syncthreads();  // previous iteration's P/V reads (and Q store) complete

        // ---- load K tile transposed: KP[d][c], and V tile natural: Vs[c][d] ----
#pragma unroll
        for (int p = 0; p < 4; p++) {
            int c = lc0 + p * 16;
            float4 kv4 = *(const float4*)(qkv + (rowbase + kv0 + lr) * C3 + koff + c);
            KP[(c + 0) * 64 + lr] = kv4.x;
            KP[(c + 1) * 64 + lr] = kv4.y;
            KP[(c + 2) * 64 + lr] = kv4.z;
            KP[(c + 3) * 64 + lr] = kv4.w;
            float4 vv4 = *(const float4*)(qkv + (rowbase + kv0 + lr) * C3 + voff + c);
            *(float4*)&Vs[lr * 64 + c] = vv4;
        }
        __syncthreads();

        // ---- S = Q K^T * scale ----
        float s[4][4];
#pragma unroll
        for (int i = 0; i < 4; i++)
#pragma unroll
            for (int j = 0; j < 4; j++) s[i][j] = 0.0f;

#pragma unroll 4
        for (int d = 0; d < 64; d++) {
            float4 kf = *(const float4*)&KP[d * 64 + tx * 4];
            float kfa[4] = {kf.x, kf.y, kf.z, kf.w};
#pragma unroll
            for (int i = 0; i < 4; i++) {
                float qv = Qs[(ty * 4 + i) * 64 + d];
#pragma unroll
                for (int j = 0; j < 4; j++)
                    s[i][j] = fmaf(qv, kfa[j], s[i][j]);
            }
        }

        const float scale = 0.125f;  // 1/sqrt(64)
#pragma unroll
        for (int i = 0; i < 4; i++)
#pragma unroll
            for (int j = 0; j < 4; j++) s[i][j] *= scale;

        // ---- causal mask (only diagonal tile is partial) ----
        if (kt == qt) {
#pragma unroll
            for (int i = 0; i < 4; i++) {
                int qg = ty * 4 + i;
#pragma unroll
                for (int j = 0; j < 4; j++) {
                    int kg = tx * 4 + j;
                    if (kg > qg) s[i][j] = -CUDART_INF_F;
                }
            }
        }

        // ---- online softmax update ----
        float p_reg[4][4];
        float f[4];
#pragma unroll
        for (int i = 0; i < 4; i++) {
            float mx = s[i][0];
#pragma unroll
            for (int j = 1; j < 4; j++) mx = fmaxf(mx, s[i][j]);
            // reduce across the 16 tx lanes (aligned 16-lane groups in warp)
            mx = fmaxf(mx, __shfl_xor_sync(0xffffffffu, mx, 8));
            mx = fmaxf(mx, __shfl_xor_sync(0xffffffffu, mx, 4));
            mx = fmaxf(mx, __shfl_xor_sync(0xffffffffu, mx, 2));
            mx = fmaxf(mx, __shfl_xor_sync(0xffffffffu, mx, 1));
            float m_new = fmaxf(m_run[i], mx);

            float rs = 0.0f;
#pragma unroll
            for (int j = 0; j < 4; j++) {
                float pv = __expf(s[i][j] - m_new);
                p_reg[i][j] = pv;
                rs += pv;
            }
            rs += __shfl_xor_sync(0xffffffffu, rs, 8);
            rs += __shfl_xor_sync(0xffffffffu, rs, 4);
            rs += __shfl_xor_sync(0xffffffffu, rs, 2);
            rs += __shfl_xor_sync(0xffffffffu, rs, 1);

            f[i] = __expf(m_run[i] - m_new);
            l_run[i] = l_run[i] * f[i] + rs;
            m_run[i] = m_new;
#pragma unroll
            for (int j = 0; j < 4; j++) O[i][j] *= f[i];
        }

        // ---- P -> shared (aliases Kt; all Kt reads are done) ----
        __syncthreads();
#pragma unroll
        for (int i = 0; i < 4; i++) {
            *(float4*)&KP[(ty * 4 + i) * 64 + tx * 4] =
                make_float4(p_reg[i][0], p_reg[i][1], p_reg[i][2], p_reg[i][3]);
        }
        __syncthreads();

        // ---- O += P @ V ----
#pragma unroll 4
        for (int k = 0; k < 64; k++) {
            float4 vf = *(const float4*)&Vs[k * 64 + tx * 4];
            float vfa[4] = {vf.x, vf.y, vf.z, vf.w};
#pragma unroll
            for (int i = 0; i < 4; i++) {
                float pf = KP[(ty * 4 + i) * 64 + k];
#pragma unroll
                for (int j = 0; j < 4; j++)
                    O[i][j] = fmaf(pf, vfa[j], O[i][j]);
            }
        }
    }

    // ---- write y[b, q0+r, h*HS + c] = O / l ----
#pragma unroll
    for (int i = 0; i < 4; i++) {
        float inv = 1.0f / l_run[i];
        float* dst = y + (rowbase + q0 + ty * 4 + i) * C_EMB + h * HS + tx * 4;
        *(float4*)dst = make_float4(O[i][0] * inv, O[i][1] * inv,
                                    O[i][2] * inv, O[i][3] * inv);
    }
}

// ---------------------------------------------------------------------------
// Launch
// ---------------------------------------------------------------------------
__global__ void get_scratch_ptrs(float** p_qkv, float** p_att) { }  // unused

extern "C" void kernel_launch(void* const* d_in, const int* in_sizes, int n_in,
                              void* d_out, int out_size)
{
    const float* x      = (const float*)d_in[0];  // [4,2048,1024]
    const float* w_attn = (const float*)d_in[1];  // [3072,1024]
    const float* w_proj = (const float*)d_in[2];  // [1024,1024]
    float* out = (float*)d_out;                   // [4,2048,1024]

    float* qkv = nullptr;
    float* att = nullptr;
    cudaGetSymbolAddress((void**)&qkv, g_qkv);
    cudaGetSymbolAddress((void**)&att, g_att);

    // 1) qkv = x @ w_attn^T   [8192, 3072]
    {
        dim3 grid(C3 / 128, MROWS / 128);
        gemm_nt_kernel<<<grid, 256>>>(x, w_attn, qkv, MROWS, C3, C_EMB);
    }

    // 2) flash attention -> att [8192, 1024] (head-interleaved = y layout)
    {
        dim3 grid(T_SEQ / 64, NH, B_SZ);
        flash_attn_kernel<<<grid, 256>>>(qkv, att);
    }

    // 3) out = att @ w_proj^T  [8192, 1024]
    {
        dim3 grid(C_EMB / 128, MROWS / 128);
        gemm_nt_kernel<<<grid, 256>>>(att, w_proj, out, MROWS, C_EMB, C_EMB);
    }
}

// round 3
// speedup vs baseline: 1.4409x; 1.4409x over previous
#include <cuda_runtime.h>
#include <cuda_bf16.h>
#include <math_constants.h>
#include <cstdint>

// Problem constants
#define B_SZ   4
#define T_SEQ  2048
#define C_EMB  1024
#define NH     16
#define HS     64
#define C3     (3 * C_EMB)           // 3072
#define MROWS  (B_SZ * T_SEQ)        // 8192

// ---------------------------------------------------------------------------
// Scratch (device globals)
// ---------------------------------------------------------------------------
__device__ float g_qkv[(size_t)MROWS * C3];
__device__ float g_att[(size_t)MROWS * C_EMB];
__device__ __nv_bfloat16 g_xhi[(size_t)MROWS * C_EMB];
__device__ __nv_bfloat16 g_xlo[(size_t)MROWS * C_EMB];
__device__ __nv_bfloat16 g_wahi[(size_t)C3 * C_EMB];
__device__ __nv_bfloat16 g_walo[(size_t)C3 * C_EMB];
__device__ __nv_bfloat16 g_wphi[(size_t)C_EMB * C_EMB];
__device__ __nv_bfloat16 g_wplo[(size_t)C_EMB * C_EMB];
__device__ __nv_bfloat16 g_ahi[(size_t)MROWS * C_EMB];
__device__ __nv_bfloat16 g_alo[(size_t)MROWS * C_EMB];

// ---------------------------------------------------------------------------
// Helpers
// ---------------------------------------------------------------------------
__device__ __forceinline__ uint32_t smem_u32(const void* p) {
    uint32_t a;
    asm("{ .reg .u64 t; cvta.to.shared.u64 t, %1; cvt.u32.u64 %0, t; }" : "=r"(a) : "l"(p));
    return a;
}

#define SW128(o) ((o) ^ (((o) >> 3) & 0x70))

__device__ __forceinline__ void cp_async16(uint32_t dst, const void* src) {
    asm volatile("cp.async.cg.shared.global [%0], [%1], 16;" :: "r"(dst), "l"(src) : "memory");
}
#define CP_COMMIT() asm volatile("cp.async.commit_group;" ::: "memory")
#define CP_WAIT(n)  asm volatile("cp.async.wait_group %0;" :: "n"(n) : "memory")

__device__ __forceinline__ void ldsm_x4(uint32_t& r0, uint32_t& r1, uint32_t& r2, uint32_t& r3,
                                        uint32_t addr) {
    asm volatile("ldmatrix.sync.aligned.m8n8.x4.shared.b16 {%0,%1,%2,%3}, [%4];"
                 : "=r"(r0), "=r"(r1), "=r"(r2), "=r"(r3) : "r"(addr));
}
__device__ __forceinline__ void ldsm_x2(uint32_t& r0, uint32_t& r1, uint32_t addr) {
    asm volatile("ldmatrix.sync.aligned.m8n8.x2.shared.b16 {%0,%1}, [%2];"
                 : "=r"(r0), "=r"(r1) : "r"(addr));
}

__device__ __forceinline__ void mma_16816(float* c, const uint32_t* a, const uint32_t* b) {
    asm volatile(
        "mma.sync.aligned.m16n8k16.row.col.f32.bf16.bf16.f32 "
        "{%0,%1,%2,%3}, {%4,%5,%6,%7}, {%8,%9}, {%0,%1,%2,%3};"
        : "+f"(c[0]), "+f"(c[1]), "+f"(c[2]), "+f"(c[3])
        : "r"(a[0]), "r"(a[1]), "r"(a[2]), "r"(a[3]), "r"(b[0]), "r"(b[1]));
}

// ---------------------------------------------------------------------------
// Split fp32 -> (hi, lo) bf16
// ---------------------------------------------------------------------------
__global__ __launch_bounds__(256) void split_kernel(
    const float* __restrict__ x, __nv_bfloat16* __restrict__ hi,
    __nv_bfloat16* __restrict__ lo, int n4)
{
    int i = blockIdx.x * blockDim.x + threadIdx.x;
    if (i >= n4) return;
    float4 v = ((const float4*)x)[i];
    __nv_bfloat16 h0 = __float2bfloat16(v.x), h1 = __float2bfloat16(v.y);
    __nv_bfloat16 h2 = __float2bfloat16(v.z), h3 = __float2bfloat16(v.w);
    __nv_bfloat16 l0 = __float2bfloat16(v.x - __bfloat162float(h0));
    __nv_bfloat16 l1 = __float2bfloat16(v.y - __bfloat162float(h1));
    __nv_bfloat16 l2 = __float2bfloat16(v.z - __bfloat162float(h2));
    __nv_bfloat16 l3 = __float2bfloat16(v.w - __bfloat162float(h3));
    ((ushort4*)hi)[i] = make_ushort4(*(uint16_t*)&h0, *(uint16_t*)&h1, *(uint16_t*)&h2, *(uint16_t*)&h3);
    ((ushort4*)lo)[i] = make_ushort4(*(uint16_t*)&l0, *(uint16_t*)&l1, *(uint16_t*)&l2, *(uint16_t*)&l3);
}

// ---------------------------------------------------------------------------
// mma.sync split-bf16 GEMM:  C[M,N] = Ah*Bh^T + Al*Bh^T + Ah*Bl^T
// All row-major, K contiguous. CTA 128x128, 8 warps (2M x 4N), warp 64x32.
// 3-stage cp.async pipeline, K-chunk 64 halfs (128B rows, SW128 swizzle).
// ---------------------------------------------------------------------------
#define STAGES   3
#define STAGE_BY 32768          // 16KB A + 16KB B

__global__ __launch_bounds__(256, 2) void gemm_mma_kernel(
    const __nv_bfloat16* __restrict__ Ah, const __nv_bfloat16* __restrict__ Al,
    const __nv_bfloat16* __restrict__ Bh, const __nv_bfloat16* __restrict__ Bl,
    float* __restrict__ C, int M, int N, int K)
{
    extern __shared__ char smem[];
    const uint32_t sbase = smem_u32(smem);
    const int tid  = threadIdx.x;
    const int wid  = tid >> 5;
    const int lane = tid & 31;
    const int warpM = wid & 1;       // 0..1
    const int warpN = wid >> 1;      // 0..3
    const int bm = blockIdx.y * 128;
    const int bn = blockIdx.x * 128;

    const int spp = K >> 6;          // stages per pass
    const int nstages = 3 * spp;

    const __nv_bfloat16* Aps[3] = {Ah, Al, Ah};
    const __nv_bfloat16* Bps[3] = {Bh, Bh, Bl};

    float acc[4][4][4];
#pragma unroll
    for (int i = 0; i < 4; i++)
#pragma unroll
        for (int j = 0; j < 4; j++)
#pragma unroll
            for (int k = 0; k < 4; k++) acc[i][j][k] = 0.0f;

    // stage issue: 4 A-chunks + 4 B-chunks of 16B per thread
    auto issue = [&](int st) {
        const int pass = st / spp;
        const int k0 = (st % spp) << 6;
        const __nv_bfloat16* Ag = Aps[pass];
        const __nv_bfloat16* Bg = Bps[pass];
        const uint32_t sA = sbase + (st % STAGES) * STAGE_BY;
        const uint32_t sB = sA + 16384;
#pragma unroll
        for (int s = 0; s < 4; s++) {
            int idx = s * 256 + tid;
            int row = idx >> 3, ch = idx & 7;
            uint32_t off = SW128(row * 128 + ch * 16);
            cp_async16(sA + off, Ag + (size_t)(bm + row) * K + k0 + ch * 8);
            cp_async16(sB + off, Bg + (size_t)(bn + row) * K + k0 + ch * 8);
        }
        CP_COMMIT();
    };

    issue(0);
    issue(1);

    for (int it = 0; it < nstages; it++) {
        CP_WAIT(1);
        __syncthreads();

        const uint32_t sA = sbase + (it % STAGES) * STAGE_BY;
        const uint32_t sB = sA + 16384;

#pragma unroll
        for (int ks = 0; ks < 4; ks++) {
            uint32_t a[4][4], b[4][2];
#pragma unroll
            for (int mt = 0; mt < 4; mt++) {
                int row = warpM * 64 + mt * 16 + (lane & 15);
                int byte = ks * 32 + ((lane >> 4) & 1) * 16;
                ldsm_x4(a[mt][0], a[mt][1], a[mt][2], a[mt][3],
                        sA + SW128(row * 128 + byte));
            }
#pragma unroll
            for (int nt = 0; nt < 4; nt++) {
                int row = warpN * 32 + nt * 8 + (lane & 7);
                int byte = ks * 32 + ((lane >> 3) & 1) * 16;
                ldsm_x2(b[nt][0], b[nt][1], sB + SW128(row * 128 + byte));
            }
#pragma unroll
            for (int mt = 0; mt < 4; mt++)
#pragma unroll
                for (int nt = 0; nt < 4; nt++)
                    mma_16816(acc[mt][nt], a[mt], b[nt]);
        }

        if (it + STAGES - 1 < nstages) issue(it + STAGES - 1);
    }

    // epilogue: direct fp32 stores
#pragma unroll
    for (int mt = 0; mt < 4; mt++) {
#pragma unroll
        for (int nt = 0; nt < 4; nt++) {
            int r0 = bm + warpM * 64 + mt * 16 + (lane >> 2);
            int c0 = bn + warpN * 32 + nt * 8 + (lane & 3) * 2;
            *(float2*)&C[(size_t)r0 * N + c0]       = make_float2(acc[mt][nt][0], acc[mt][nt][1]);
            *(float2*)&C[(size_t)(r0 + 8) * N + c0] = make_float2(acc[mt][nt][2], acc[mt][nt][3]);
        }
    }
}

// ---------------------------------------------------------------------------
// Flash attention, causal, fp32 (unchanged)
// ---------------------------------------------------------------------------
__global__ __launch_bounds__(256) void flash_attn_kernel(
    const float* __restrict__ qkv, float* __restrict__ y)
{
    __shared__ float Qs[64 * 64];
    __shared__ float KP[64 * 64];
    __shared__ float Vs[64 * 64];

    const int qt = blockIdx.x;
    const int h  = blockIdx.y;
    const int b  = blockIdx.z;
    const int tid = threadIdx.x;
    const int ty = tid >> 4;
    const int tx = tid & 15;
    const int q0 = qt * 64;

    const size_t rowbase = (size_t)b * T_SEQ;
    const size_t qoff = (size_t)h * HS;
    const size_t koff = (size_t)C_EMB + h * HS;
    const size_t voff = (size_t)2 * C_EMB + h * HS;

    const int lr  = tid >> 2;
    const int lc0 = (tid & 3) * 4;

#pragma unroll
    for (int p = 0; p < 4; p++) {
        int c = lc0 + p * 16;
        float4 v = *(const float4*)(qkv + (rowbase + q0 + lr) * C3 + qoff + c);
        *(float4*)&Qs[lr * 64 + c] = v;
    }

    float m_run[4], l_run[4], O[4][4];
#pragma unroll
    for (int i = 0; i < 4; i++) {
        m_run[i] = -CUDART_INF_F;
        l_run[i] = 0.0f;
#pragma unroll
        for (int j = 0; j < 4; j++) O[i][j] = 0.0f;
    }

    for (int kt = 0; kt <= qt; kt++) {
        const int kv0 = kt * 64;
        __syncthreads();
#pragma unroll
        for (int p = 0; p < 4; p++) {
            int c = lc0 + p * 16;
            float4 kv4 = *(const float4*)(qkv + (rowbase + kv0 + lr) * C3 + koff + c);
            KP[(c + 0) * 64 + lr] = kv4.x;
            KP[(c + 1) * 64 + lr] = kv4.y;
            KP[(c + 2) * 64 + lr] = kv4.z;
            KP[(c + 3) * 64 + lr] = kv4.w;
            float4 vv4 = *(const float4*)(qkv + (rowbase + kv0 + lr) * C3 + voff + c);
            *(float4*)&Vs[lr * 64 + c] = vv4;
        }
        __syncthreads();

        float s[4][4];
#pragma unroll
        for (int i = 0; i < 4; i++)
#pragma unroll
            for (int j = 0; j < 4; j++) s[i][j] = 0.0f;

#pragma unroll 4
        for (int d = 0; d < 64; d++) {
            float4 kf = *(const float4*)&KP[d * 64 + tx * 4];
            float kfa[4] = {kf.x, kf.y, kf.z, kf.w};
#pragma unroll
            for (int i = 0; i < 4; i++) {
                float qv = Qs[(ty * 4 + i) * 64 + d];
#pragma unroll
                for (int j = 0; j < 4; j++)
                    s[i][j] = fmaf(qv, kfa[j], s[i][j]);
            }
        }

        const float scale = 0.125f;
#pragma unroll
        for (int i = 0; i < 4; i++)
#pragma unroll
            for (int j = 0; j < 4; j++) s[i][j] *= scale;

        if (kt == qt) {
#pragma unroll
            for (int i = 0; i < 4; i++) {
                int qg = ty * 4 + i;
#pragma unroll
                for (int j = 0; j < 4; j++) {
                    int kg = tx * 4 + j;
                    if (kg > qg) s[i][j] = -CUDART_INF_F;
                }
            }
        }

        float p_reg[4][4];
#pragma unroll
        for (int i = 0; i < 4; i++) {
            float mx = s[i][0];
#pragma unroll
            for (int j = 1; j < 4; j++) mx = fmaxf(mx, s[i][j]);
            mx = fmaxf(mx, __shfl_xor_sync(0xffffffffu, mx, 8));
            mx = fmaxf(mx, __shfl_xor_sync(0xffffffffu, mx, 4));
            mx = fmaxf(mx, __shfl_xor_sync(0xffffffffu, mx, 2));
            mx = fmaxf(mx, __shfl_xor_sync(0xffffffffu, mx, 1));
            float m_new = fmaxf(m_run[i], mx);

            float rs = 0.0f;
#pragma unroll
            for (int j = 0; j < 4; j++) {
                float pv = __expf(s[i][j] - m_new);
                p_reg[i][j] = pv;
                rs += pv;
            }
            rs += __shfl_xor_sync(0xffffffffu, rs, 8);
            rs += __shfl_xor_sync(0xffffffffu, rs, 4);
            rs += __shfl_xor_sync(0xffffffffu, rs, 2);
            rs += __shfl_xor_sync(0xffffffffu, rs, 1);

            float f = __expf(m_run[i] - m_new);
            l_run[i] = l_run[i] * f + rs;
            m_run[i] = m_new;
#pragma unroll
            for (int j = 0; j < 4; j++) O[i][j] *= f;
        }

        __syncthreads();
#pragma unroll
        for (int i = 0; i < 4; i++) {
            *(float4*)&KP[(ty * 4 + i) * 64 + tx * 4] =
                make_float4(p_reg[i][0], p_reg[i][1], p_reg[i][2], p_reg[i][3]);
        }
        __syncthreads();

#pragma unroll 4
        for (int k = 0; k < 64; k++) {
            float4 vf = *(const float4*)&Vs[k * 64 + tx * 4];
            float vfa[4] = {vf.x, vf.y, vf.z, vf.w};
#pragma unroll
            for (int i = 0; i < 4; i++) {
                float pf = KP[(ty * 4 + i) * 64 + k];
#pragma unroll
                for (int j = 0; j < 4; j++)
                    O[i][j] = fmaf(pf, vfa[j], O[i][j]);
            }
        }
    }

#pragma unroll
    for (int i = 0; i < 4; i++) {
        float inv = 1.0f / l_run[i];
        float* dst = y + (rowbase + q0 + ty * 4 + i) * C_EMB + h * HS + tx * 4;
        *(float4*)dst = make_float4(O[i][0] * inv, O[i][1] * inv,
                                    O[i][2] * inv, O[i][3] * inv);
    }
}

// ---------------------------------------------------------------------------
// Launch
// ---------------------------------------------------------------------------
extern "C" void kernel_launch(void* const* d_in, const int* in_sizes, int n_in,
                              void* d_out, int out_size)
{
    const float* x      = (const float*)d_in[0];
    const float* w_attn = (const float*)d_in[1];
    const float* w_proj = (const float*)d_in[2];
    float* out = (float*)d_out;

    float *qkv, *att;
    __nv_bfloat16 *xhi, *xlo, *wahi, *walo, *wphi, *wplo, *ahi, *alo;
    cudaGetSymbolAddress((void**)&qkv, g_qkv);
    cudaGetSymbolAddress((void**)&att, g_att);
    cudaGetSymbolAddress((void**)&xhi, g_xhi);
    cudaGetSymbolAddress((void**)&xlo, g_xlo);
    cudaGetSymbolAddress((void**)&wahi, g_wahi);
    cudaGetSymbolAddress((void**)&walo, g_walo);
    cudaGetSymbolAddress((void**)&wphi, g_wphi);
    cudaGetSymbolAddress((void**)&wplo, g_wplo);
    cudaGetSymbolAddress((void**)&ahi, g_ahi);
    cudaGetSymbolAddress((void**)&alo, g_alo);

    const int smem_bytes = STAGES * STAGE_BY;   // 96 KB
    cudaFuncSetAttribute(gemm_mma_kernel, cudaFuncAttributeMaxDynamicSharedMemorySize, smem_bytes);

    // splits
    {
        int n4 = MROWS * C_EMB / 4;
        split_kernel<<<(n4 + 255) / 256, 256>>>(x, xhi, xlo, n4);
        int n4w = C3 * C_EMB / 4;
        split_kernel<<<(n4w + 255) / 256, 256>>>(w_attn, wahi, walo, n4w);
        int n4p = C_EMB * C_EMB / 4;
        split_kernel<<<(n4p + 255) / 256, 256>>>(w_proj, wphi, wplo, n4p);
    }

    // 1) qkv = x @ w_attn^T
    {
        dim3 grid(C3 / 128, MROWS / 128);
        gemm_mma_kernel<<<grid, 256, smem_bytes>>>(xhi, xlo, wahi, walo, qkv, MROWS, C3, C_EMB);
    }

    // 2) flash attention (fp32)
    {
        dim3 grid(T_SEQ / 64, NH, B_SZ);
        flash_attn_kernel<<<grid, 256>>>(qkv, att);
    }

    // split attention output
    {
        int n4 = MROWS * C_EMB / 4;
        split_kernel<<<(n4 + 255) / 256, 256>>>(att, ahi, alo, n4);
    }

    // 3) out = att @ w_proj^T
    {
        dim3 grid(C_EMB / 128, MROWS / 128);
        gemm_mma_kernel<<<grid, 256, smem_bytes>>>(ahi, alo, wphi, wplo, out, MROWS, C_EMB, C_EMB);
    }
}

// round 6
// speedup vs baseline: 2.8656x; 1.9887x over previous
#include <cuda_runtime.h>
#include <cuda_bf16.h>
#include <math_constants.h>
#include <cstdint>

// Problem constants
#define B_SZ   4
#define T_SEQ  2048
#define C_EMB  1024
#define NH     16
#define HS     64
#define C3     (3 * C_EMB)           // 3072
#define MROWS  (B_SZ * T_SEQ)        // 8192

// ---------------------------------------------------------------------------
// Scratch (device globals)
// ---------------------------------------------------------------------------
__device__ __nv_bfloat16 g_xhi[(size_t)MROWS * C_EMB];
__device__ __nv_bfloat16 g_xlo[(size_t)MROWS * C_EMB];
__device__ __nv_bfloat16 g_wahi[(size_t)C3 * C_EMB];
__device__ __nv_bfloat16 g_walo[(size_t)C3 * C_EMB];
__device__ __nv_bfloat16 g_wphi[(size_t)C_EMB * C_EMB];
__device__ __nv_bfloat16 g_wplo[(size_t)C_EMB * C_EMB];
__device__ __nv_bfloat16 g_qkvhi[(size_t)MROWS * C3];
__device__ __nv_bfloat16 g_qkvlo[(size_t)MROWS * C3];
__device__ __nv_bfloat16 g_ahi[(size_t)MROWS * C_EMB];
__device__ __nv_bfloat16 g_alo[(size_t)MROWS * C_EMB];

// ---------------------------------------------------------------------------
// Helpers
// ---------------------------------------------------------------------------
__device__ __forceinline__ uint32_t smem_u32(const void* p) {
    uint32_t a;
    asm("{ .reg .u64 t; cvta.to.shared.u64 t, %1; cvt.u32.u64 %0, t; }" : "=r"(a) : "l"(p));
    return a;
}

#define SW128(o) ((o) ^ (((o) >> 3) & 0x70))

__device__ __forceinline__ void cp_async16(uint32_t dst, const void* src) {
    asm volatile("cp.async.cg.shared.global [%0], [%1], 16;" :: "r"(dst), "l"(src) : "memory");
}
#define CP_COMMIT() asm volatile("cp.async.commit_group;" ::: "memory")
#define CP_WAIT(n)  asm volatile("cp.async.wait_group %0;" :: "n"(n) : "memory")

__device__ __forceinline__ void ldsm_x4(uint32_t& r0, uint32_t& r1, uint32_t& r2, uint32_t& r3,
                                        uint32_t addr) {
    asm volatile("ldmatrix.sync.aligned.m8n8.x4.shared.b16 {%0,%1,%2,%3}, [%4];"
                 : "=r"(r0), "=r"(r1), "=r"(r2), "=r"(r3) : "r"(addr));
}
__device__ __forceinline__ void ldsm_x2(uint32_t& r0, uint32_t& r1, uint32_t addr) {
    asm volatile("ldmatrix.sync.aligned.m8n8.x2.shared.b16 {%0,%1}, [%2];"
                 : "=r"(r0), "=r"(r1) : "r"(addr));
}
__device__ __forceinline__ void ldsm_x4t(uint32_t& r0, uint32_t& r1, uint32_t& r2, uint32_t& r3,
                                         uint32_t addr) {
    asm volatile("ldmatrix.sync.aligned.m8n8.x4.trans.shared.b16 {%0,%1,%2,%3}, [%4];"
                 : "=r"(r0), "=r"(r1), "=r"(r2), "=r"(r3) : "r"(addr));
}

__device__ __forceinline__ void mma_16816(float* c, const uint32_t* a, const uint32_t* b) {
    asm volatile(
        "mma.sync.aligned.m16n8k16.row.col.f32.bf16.bf16.f32 "
        "{%0,%1,%2,%3}, {%4,%5,%6,%7}, {%8,%9}, {%0,%1,%2,%3};"
        : "+f"(c[0]), "+f"(c[1]), "+f"(c[2]), "+f"(c[3])
        : "r"(a[0]), "r"(a[1]), "r"(a[2]), "r"(a[3]), "r"(b[0]), "r"(b[1]));
}

__device__ __forceinline__ uint32_t pack_bf16x2(float a, float b) {
    __nv_bfloat162 t = __floats2bfloat162_rn(a, b);   // low = a
    return *(uint32_t*)&t;
}

// ---------------------------------------------------------------------------
// Split fp32 -> (hi, lo) bf16
// ---------------------------------------------------------------------------
__global__ __launch_bounds__(256) void split_kernel(
    const float* __restrict__ x, __nv_bfloat16* __restrict__ hi,
    __nv_bfloat16* __restrict__ lo, int n4)
{
    int i = blockIdx.x * blockDim.x + threadIdx.x;
    if (i >= n4) return;
    float4 v = ((const float4*)x)[i];
    __nv_bfloat16 h0 = __float2bfloat16(v.x), h1 = __float2bfloat16(v.y);
    __nv_bfloat16 h2 = __float2bfloat16(v.z), h3 = __float2bfloat16(v.w);
    __nv_bfloat16 l0 = __float2bfloat16(v.x - __bfloat162float(h0));
    __nv_bfloat16 l1 = __float2bfloat16(v.y - __bfloat162float(h1));
    __nv_bfloat16 l2 = __float2bfloat16(v.z - __bfloat162float(h2));
    __nv_bfloat16 l3 = __float2bfloat16(v.w - __bfloat162float(h3));
    ((ushort4*)hi)[i] = make_ushort4(*(uint16_t*)&h0, *(uint16_t*)&h1, *(uint16_t*)&h2, *(uint16_t*)&h3);
    ((ushort4*)lo)[i] = make_ushort4(*(uint16_t*)&l0, *(uint16_t*)&l1, *(uint16_t*)&l2, *(uint16_t*)&l3);
}

// ---------------------------------------------------------------------------
// mma.sync split-bf16 GEMM:  C = Ah*Bh^T + Al*Bh^T + Ah*Bl^T
// CTA 128x128, 8 warps (2M x 4N), 3-stage cp.async.
// BF16OUT: write hi/lo bf16 split instead of fp32.
// ---------------------------------------------------------------------------
#define STAGES   3
#define STAGE_BY 32768

template<bool BF16OUT>
__global__ __launch_bounds__(256, 2) void gemm_mma_kernel(
    const __nv_bfloat16* __restrict__ Ah, const __nv_bfloat16* __restrict__ Al,
    const __nv_bfloat16* __restrict__ Bh, const __nv_bfloat16* __restrict__ Bl,
    float* __restrict__ C, __nv_bfloat16* __restrict__ Chi, __nv_bfloat16* __restrict__ Clo,
    int M, int N, int K)
{
    extern __shared__ char smem[];
    const uint32_t sbase = smem_u32(smem);
    const int tid  = threadIdx.x;
    const int wid  = tid >> 5;
    const int lane = tid & 31;
    const int warpM = wid & 1;
    const int warpN = wid >> 1;
    const int bm = blockIdx.y * 128;
    const int bn = blockIdx.x * 128;

    const int spp = K >> 6;
    const int nstages = 3 * spp;

    const __nv_bfloat16* Aps[3] = {Ah, Al, Ah};
    const __nv_bfloat16* Bps[3] = {Bh, Bh, Bl};

    float acc[4][4][4];
#pragma unroll
    for (int i = 0; i < 4; i++)
#pragma unroll
        for (int j = 0; j < 4; j++)
#pragma unroll
            for (int k = 0; k < 4; k++) acc[i][j][k] = 0.0f;

    auto issue = [&](int st) {
        const int pass = st / spp;
        const int k0 = (st % spp) << 6;
        const __nv_bfloat16* Ag = Aps[pass];
        const __nv_bfloat16* Bg = Bps[pass];
        const uint32_t sA = sbase + (st % STAGES) * STAGE_BY;
        const uint32_t sB = sA + 16384;
#pragma unroll
        for (int s = 0; s < 4; s++) {
            int idx = s * 256 + tid;
            int row = idx >> 3, ch = idx & 7;
            uint32_t off = SW128(row * 128 + ch * 16);
            cp_async16(sA + off, Ag + (size_t)(bm + row) * K + k0 + ch * 8);
            cp_async16(sB + off, Bg + (size_t)(bn + row) * K + k0 + ch * 8);
        }
        CP_COMMIT();
    };

    issue(0);
    issue(1);

    for (int it = 0; it < nstages; it++) {
        CP_WAIT(1);
        __syncthreads();

        const uint32_t sA = sbase + (it % STAGES) * STAGE_BY;
        const uint32_t sB = sA + 16384;

#pragma unroll
        for (int ks = 0; ks < 4; ks++) {
            uint32_t a[4][4], b[4][2];
#pragma unroll
            for (int mt = 0; mt < 4; mt++) {
                int row = warpM * 64 + mt * 16 + (lane & 15);
                int byte = ks * 32 + ((lane >> 4) & 1) * 16;
                ldsm_x4(a[mt][0], a[mt][1], a[mt][2], a[mt][3],
                        sA + SW128(row * 128 + byte));
            }
#pragma unroll
            for (int nt = 0; nt < 4; nt++) {
                int row = warpN * 32 + nt * 8 + (lane & 7);
                int byte = ks * 32 + ((lane >> 3) & 1) * 16;
                ldsm_x2(b[nt][0], b[nt][1], sB + SW128(row * 128 + byte));
            }
#pragma unroll
            for (int mt = 0; mt < 4; mt++)
#pragma unroll
                for (int nt = 0; nt < 4; nt++)
                    mma_16816(acc[mt][nt], a[mt], b[nt]);
        }

        if (it + STAGES - 1 < nstages) issue(it + STAGES - 1);
    }

#pragma unroll
    for (int mt = 0; mt < 4; mt++) {
#pragma unroll
        for (int nt = 0; nt < 4; nt++) {
            int r0 = bm + warpM * 64 + mt * 16 + (lane >> 2);
            int c0 = bn + warpN * 32 + nt * 8 + (lane & 3) * 2;
            if (BF16OUT) {
#pragma unroll
                for (int half = 0; half < 2; half++) {
                    float v0 = acc[mt][nt][half * 2 + 0];
                    float v1 = acc[mt][nt][half * 2 + 1];
                    __nv_bfloat16 h0 = __float2bfloat16(v0), h1 = __float2bfloat16(v1);
                    float l0 = v0 - __bfloat162float(h0), l1 = v1 - __bfloat162float(h1);
                    size_t off = (size_t)(r0 + half * 8) * N + c0;
                    *(uint32_t*)&Chi[off] = ((uint32_t)*(uint16_t*)&h1 << 16) | *(uint16_t*)&h0;
                    __nv_bfloat16 b0 = __float2bfloat16(l0), b1 = __float2bfloat16(l1);
                    *(uint32_t*)&Clo[off] = ((uint32_t)*(uint16_t*)&b1 << 16) | *(uint16_t*)&b0;
                }
            } else {
                *(float2*)&C[(size_t)r0 * N + c0]       = make_float2(acc[mt][nt][0], acc[mt][nt][1]);
                *(float2*)&C[(size_t)(r0 + 8) * N + c0] = make_float2(acc[mt][nt][2], acc[mt][nt][3]);
            }
        }
    }
}

// ---------------------------------------------------------------------------
// Flash attention, causal, mma.sync split-bf16.
// CTA = 128 q-rows x (b,h). 8 warps x 16 rows. K-tile 64, 3-stage cp.async.
// Reads qkv hi/lo bf16; writes attention output hi/lo bf16.
// ---------------------------------------------------------------------------
#define AT_QBY    32768                 // Qhi 16K + Qlo 16K
#define AT_STBY   32768                 // Khi/Klo/Vhi/Vlo 8K each
#define AT_SMEM   (AT_QBY + 3 * AT_STBY)  // 128 KB

__global__ __launch_bounds__(256) void attn_mma_kernel(
    const __nv_bfloat16* __restrict__ qh_g, const __nv_bfloat16* __restrict__ ql_g,
    __nv_bfloat16* __restrict__ yhi, __nv_bfloat16* __restrict__ ylo)
{
    extern __shared__ char smem[];
    const uint32_t sbase = smem_u32(smem);
    const int tid  = threadIdx.x;
    const int wid  = tid >> 5;
    const int lane = tid & 31;
    const int qt = blockIdx.x;          // 0..15 (128-row q tiles)
    const int h  = blockIdx.y;
    const int b  = blockIdx.z;
    const int q0 = qt * 128;
    const size_t rowbase = (size_t)b * T_SEQ;

    const uint32_t sQh = sbase;
    const uint32_t sQl = sbase + 16384;

    // ---- issue Q loads (group with stage 0) ----
    {
        const __nv_bfloat16* srch = qh_g + (rowbase + q0) * C3 + h * HS;
        const __nv_bfloat16* srcl = ql_g + (rowbase + q0) * C3 + h * HS;
#pragma unroll
        for (int s = 0; s < 4; s++) {
            int idx = s * 256 + tid;
            int row = idx >> 3, ch = idx & 7;
            uint32_t off = SW128(row * 128 + ch * 16);
            cp_async16(sQh + off, srch + (size_t)row * C3 + ch * 8);
            cp_async16(sQl + off, srcl + (size_t)row * C3 + ch * 8);
        }
    }

    const int nkt = 2 * qt + 2;

    auto issue_kv = [&](int kt) {
        if (kt < nkt) {
            const int key0 = kt * 64;
            const uint32_t st = sbase + AT_QBY + (kt % 3) * AT_STBY;
            const __nv_bfloat16* kh = qh_g + (rowbase + key0) * C3 + C_EMB + h * HS;
            const __nv_bfloat16* kl = ql_g + (rowbase + key0) * C3 + C_EMB + h * HS;
            const __nv_bfloat16* vh = qh_g + (rowbase + key0) * C3 + 2 * C_EMB + h * HS;
            const __nv_bfloat16* vl = ql_g + (rowbase + key0) * C3 + 2 * C_EMB + h * HS;
#pragma unroll
            for (int s = 0; s < 2; s++) {
                int idx = s * 256 + tid;
                int row = idx >> 3, ch = idx & 7;
                uint32_t off = SW128(row * 128 + ch * 16);
                size_t g = (size_t)row * C3 + ch * 8;
                cp_async16(st + off, kh + g);
                cp_async16(st + 8192 + off, kl + g);
                cp_async16(st + 16384 + off, vh + g);
                cp_async16(st + 24576 + off, vl + g);
            }
        }
        CP_COMMIT();
    };

    issue_kv(0);   // group 0 (Q + stage0)
    issue_kv(1);   // group 1

    float O[8][4];
#pragma unroll
    for (int d = 0; d < 8; d++)
#pragma unroll
        for (int e = 0; e < 4; e++) O[d][e] = 0.0f;
    float m_run[2] = {-1e30f, -1e30f};
    float l_run[2] = {0.0f, 0.0f};

    const int warp16 = wid * 16;

    for (int kt = 0; kt < nkt; kt++) {
        CP_WAIT(1);
        __syncthreads();
        issue_kv(kt + 2);

        const int key0 = kt * 64;
        const uint32_t st  = sbase + AT_QBY + (kt % 3) * AT_STBY;
        const uint32_t sKh = st, sKl = st + 8192, sVh = st + 16384, sVl = st + 24576;

        // ---- S = Qh*Kh^T + Ql*Kh^T + Qh*Kl^T ----
        float S[8][4];
#pragma unroll
        for (int n = 0; n < 8; n++)
#pragma unroll
            for (int e = 0; e < 4; e++) S[n][e] = 0.0f;

#pragma unroll
        for (int kc = 0; kc < 4; kc++) {
            uint32_t qh[4], ql[4];
            {
                int row = warp16 + (lane & 15);
                int byte = kc * 32 + ((lane >> 4) & 1) * 16;
                ldsm_x4(qh[0], qh[1], qh[2], qh[3], sQh + SW128(row * 128 + byte));
                ldsm_x4(ql[0], ql[1], ql[2], ql[3], sQl + SW128(row * 128 + byte));
            }
#pragma unroll
            for (int ntp = 0; ntp < 4; ntp++) {
                uint32_t kh[4], kl[4];
                int krow = ntp * 16 + (lane & 7) + ((lane & 16) >> 1);
                int kbyte = kc * 32 + ((lane >> 3) & 1) * 16;
                ldsm_x4(kh[0], kh[1], kh[2], kh[3], sKh + SW128(krow * 128 + kbyte));
                ldsm_x4(kl[0], kl[1], kl[2], kl[3], sKl + SW128(krow * 128 + kbyte));
                mma_16816(S[2 * ntp],     qh, kh);
                mma_16816(S[2 * ntp],     ql, kh);
                mma_16816(S[2 * ntp],     qh, kl);
                mma_16816(S[2 * ntp + 1], qh, kh + 2);
                mma_16816(S[2 * ntp + 1], ql, kh + 2);
                mma_16816(S[2 * ntp + 1], qh, kl + 2);
            }
        }

        // ---- scale + causal mask ----
#pragma unroll
        for (int n = 0; n < 8; n++)
#pragma unroll
            for (int e = 0; e < 4; e++) S[n][e] *= 0.125f;

        if (kt >= 2 * qt) {
            int qrow = q0 + warp16 + (lane >> 2);
#pragma unroll
            for (int n = 0; n < 8; n++) {
                int key = key0 + n * 8 + (lane & 3) * 2;
                if (key     > qrow)     S[n][0] = -1e30f;
                if (key + 1 > qrow)     S[n][1] = -1e30f;
                if (key     > qrow + 8) S[n][2] = -1e30f;
                if (key + 1 > qrow + 8) S[n][3] = -1e30f;
            }
        }

        // ---- online softmax (rows lane>>2 and lane>>2 + 8) ----
        float mx0 = S[0][0], mx1 = S[0][2];
#pragma unroll
        for (int n = 0; n < 8; n++) {
            mx0 = fmaxf(mx0, fmaxf(S[n][0], S[n][1]));
            mx1 = fmaxf(mx1, fmaxf(S[n][2], S[n][3]));
        }
        mx0 = fmaxf(mx0, __shfl_xor_sync(0xffffffffu, mx0, 1));
        mx0 = fmaxf(mx0, __shfl_xor_sync(0xffffffffu, mx0, 2));
        mx1 = fmaxf(mx1, __shfl_xor_sync(0xffffffffu, mx1, 1));
        mx1 = fmaxf(mx1, __shfl_xor_sync(0xffffffffu, mx1, 2));

        float mn0 = fmaxf(m_run[0], mx0);
        float mn1 = fmaxf(m_run[1], mx1);
        float f0 = __expf(m_run[0] - mn0);
        float f1 = __expf(m_run[1] - mn1);
        m_run[0] = mn0; m_run[1] = mn1;

        float rs0 = 0.0f, rs1 = 0.0f;
#pragma unroll
        for (int n = 0; n < 8; n++) {
            S[n][0] = __expf(S[n][0] - mn0);
            S[n][1] = __expf(S[n][1] - mn0);
            S[n][2] = __expf(S[n][2] - mn1);
            S[n][3] = __expf(S[n][3] - mn1);
            rs0 += S[n][0] + S[n][1];
            rs1 += S[n][2] + S[n][3];
        }
        rs0 += __shfl_xor_sync(0xffffffffu, rs0, 1);
        rs0 += __shfl_xor_sync(0xffffffffu, rs0, 2);
        rs1 += __shfl_xor_sync(0xffffffffu, rs1, 1);
        rs1 += __shfl_xor_sync(0xffffffffu, rs1, 2);
        l_run[0] = l_run[0] * f0 + rs0;
        l_run[1] = l_run[1] * f1 + rs1;

#pragma unroll
        for (int d = 0; d < 8; d++) {
            O[d][0] *= f0; O[d][1] *= f0;
            O[d][2] *= f1; O[d][3] *= f1;
        }

        // ---- build P fragments (hi + lo) in registers ----
        // part->(n,e) mapping yields exactly [a0,a1,a2,a3]:
        //   part0: n=2kc,  e=0 -> a0=(r,   k_lo)   part1: n=2kc,  e=2 -> a1=(r+8, k_lo)
        //   part2: n=2kc+1,e=0 -> a2=(r,   k_hi)   part3: n=2kc+1,e=2 -> a3=(r+8, k_hi)
        uint32_t ph[4][4], pl[4][4];
#pragma unroll
        for (int kc = 0; kc < 4; kc++) {
#pragma unroll
            for (int part = 0; part < 4; part++) {
                int n = 2 * kc + (part >> 1);
                int e = (part & 1) * 2;
                float v0 = S[n][e], v1 = S[n][e + 1];
                __nv_bfloat16 h0 = __float2bfloat16(v0), h1 = __float2bfloat16(v1);
                ph[kc][part] = ((uint32_t)*(uint16_t*)&h1 << 16) | *(uint16_t*)&h0;
                pl[kc][part] = pack_bf16x2(v0 - __bfloat162float(h0), v1 - __bfloat162float(h1));
            }
        }

        // ---- O += Ph*Vh + Pl*Vh + Ph*Vl ----
#pragma unroll
        for (int dt = 0; dt < 8; dt++) {
            uint32_t vh[8], vl[8];
            ldsm_x4t(vh[0], vh[1], vh[2], vh[3], sVh + SW128(lane * 128 + dt * 16));
            ldsm_x4t(vh[4], vh[5], vh[6], vh[7], sVh + SW128((32 + lane) * 128 + dt * 16));
            ldsm_x4t(vl[0], vl[1], vl[2], vl[3], sVl + SW128(lane * 128 + dt * 16));
            ldsm_x4t(vl[4], vl[5], vl[6], vl[7], sVl + SW128((32 + lane) * 128 + dt * 16));
#pragma unroll
            for (int kc = 0; kc < 4; kc++) {
                mma_16816(O[dt], ph[kc], vh + 2 * kc);
                mma_16816(O[dt], pl[kc], vh + 2 * kc);
                mma_16816(O[dt], ph[kc], vl + 2 * kc);
            }
        }
        __syncthreads();
    }

    // ---- epilogue: write hi/lo bf16 split of O / l ----
    float inv0 = 1.0f / l_run[0];
    float inv1 = 1.0f / l_run[1];
    int r0 = q0 + warp16 + (lane >> 2);
#pragma unroll
    for (int dt = 0; dt < 8; dt++) {
        int col = h * HS + dt * 8 + (lane & 3) * 2;
        float v0 = O[dt][0] * inv0, v1 = O[dt][1] * inv0;
        float v2 = O[dt][2] * inv1, v3 = O[dt][3] * inv1;
        __nv_bfloat16 h0 = __float2bfloat16(v0), h1 = __float2bfloat16(v1);
        __nv_bfloat16 h2 = __float2bfloat16(v2), h3 = __float2bfloat16(v3);
        size_t o0 = (rowbase + r0) * C_EMB + col;
        size_t o1 = (rowbase + r0 + 8) * C_EMB + col;
        *(uint32_t*)&yhi[o0] = ((uint32_t)*(uint16_t*)&h1 << 16) | *(uint16_t*)&h0;
        *(uint32_t*)&yhi[o1] = ((uint32_t)*(uint16_t*)&h3 << 16) | *(uint16_t*)&h2;
        *(uint32_t*)&ylo[o0] = pack_bf16x2(v0 - __bfloat162float(h0), v1 - __bfloat162float(h1));
        *(uint32_t*)&ylo[o1] = pack_bf16x2(v2 - __bfloat162float(h2), v3 - __bfloat162float(h3));
    }
}

// ---------------------------------------------------------------------------
// Launch
// ---------------------------------------------------------------------------
extern "C" void kernel_launch(void* const* d_in, const int* in_sizes, int n_in,
                              void* d_out, int out_size)
{
    const float* x      = (const float*)d_in[0];
    const float* w_attn = (const float*)d_in[1];
    const float* w_proj = (const float*)d_in[2];
    float* out = (float*)d_out;

    __nv_bfloat16 *xhi, *xlo, *wahi, *walo, *wphi, *wplo, *qkvhi, *qkvlo, *ahi, *alo;
    cudaGetSymbolAddress((void**)&xhi, g_xhi);
    cudaGetSymbolAddress((void**)&xlo, g_xlo);
    cudaGetSymbolAddress((void**)&wahi, g_wahi);
    cudaGetSymbolAddress((void**)&walo, g_walo);
    cudaGetSymbolAddress((void**)&wphi, g_wphi);
    cudaGetSymbolAddress((void**)&wplo, g_wplo);
    cudaGetSymbolAddress((void**)&qkvhi, g_qkvhi);
    cudaGetSymbolAddress((void**)&qkvlo, g_qkvlo);
    cudaGetSymbolAddress((void**)&ahi, g_ahi);
    cudaGetSymbolAddress((void**)&alo, g_alo);

    const int smem_gemm = STAGES * STAGE_BY;
    cudaFuncSetAttribute(gemm_mma_kernel<true>,  cudaFuncAttributeMaxDynamicSharedMemorySize, smem_gemm);
    cudaFuncSetAttribute(gemm_mma_kernel<false>, cudaFuncAttributeMaxDynamicSharedMemorySize, smem_gemm);
    cudaFuncSetAttribute(attn_mma_kernel, cudaFuncAttributeMaxDynamicSharedMemorySize, AT_SMEM);

    // splits of inputs
    {
        int n4 = MROWS * C_EMB / 4;
        split_kernel<<<(n4 + 255) / 256, 256>>>(x, xhi, xlo, n4);
        int n4w = C3 * C_EMB / 4;
        split_kernel<<<(n4w + 255) / 256, 256>>>(w_attn, wahi, walo, n4w);
        int n4p = C_EMB * C_EMB / 4;
        split_kernel<<<(n4p + 255) / 256, 256>>>(w_proj, wphi, wplo, n4p);
    }

    // 1) qkv (bf16 hi/lo out)
    {
        dim3 grid(C3 / 128, MROWS / 128);
        gemm_mma_kernel<true><<<grid, 256, smem_gemm>>>(
            xhi, xlo, wahi, walo, nullptr, qkvhi, qkvlo, MROWS, C3, C_EMB);
    }

    // 2) flash attention (mma.sync, split bf16) -> ahi/alo
    {
        dim3 grid(T_SEQ / 128, NH, B_SZ);
        attn_mma_kernel<<<grid, 256, AT_SMEM>>>(qkvhi, qkvlo, ahi, alo);
    }

    // 3) out = att @ w_proj^T (fp32 out)
    {
        dim3 grid(C_EMB / 128, MROWS / 128);
        gemm_mma_kernel<false><<<grid, 256, smem_gemm>>>(
            ahi, alo, wphi, wplo, out, nullptr, nullptr, MROWS, C_EMB, C_EMB);
    }
}

// round 7
// speedup vs baseline: 3.6186x; 1.2628x over previous
#include <cuda_runtime.h>
#include <cuda_bf16.h>
#include <math_constants.h>
#include <cstdint>

// Problem constants
#define B_SZ   4
#define T_SEQ  2048
#define C_EMB  1024
#define NH     16
#define HS     64
#define C3     (3 * C_EMB)           // 3072
#define MROWS  (B_SZ * T_SEQ)        // 8192

// ---------------------------------------------------------------------------
// Scratch (device globals)
// ---------------------------------------------------------------------------
__device__ float g_xt[(size_t)MROWS * C_EMB];        // tf32-rounded x
__device__ float g_wat[(size_t)C3 * C_EMB];          // tf32-rounded w_attn
__device__ float g_wpt[(size_t)C_EMB * C_EMB];       // tf32-rounded w_proj
__device__ __nv_bfloat16 g_qkvhi[(size_t)MROWS * C3];
__device__ __nv_bfloat16 g_qkvlo[(size_t)MROWS * C3];
__device__ float g_att[(size_t)MROWS * C_EMB];       // tf32-rounded attention out

// ---------------------------------------------------------------------------
// Helpers
// ---------------------------------------------------------------------------
__device__ __forceinline__ uint32_t smem_u32(const void* p) {
    uint32_t a;
    asm("{ .reg .u64 t; cvta.to.shared.u64 t, %1; cvt.u32.u64 %0, t; }" : "=r"(a) : "l"(p));
    return a;
}

#define SW128(o) ((o) ^ (((o) >> 3) & 0x70))

__device__ __forceinline__ void cp_async16(uint32_t dst, const void* src) {
    asm volatile("cp.async.cg.shared.global [%0], [%1], 16;" :: "r"(dst), "l"(src) : "memory");
}
#define CP_COMMIT() asm volatile("cp.async.commit_group;" ::: "memory")
#define CP_WAIT(n)  asm volatile("cp.async.wait_group %0;" :: "n"(n) : "memory")

__device__ __forceinline__ void ldsm_x4(uint32_t& r0, uint32_t& r1, uint32_t& r2, uint32_t& r3,
                                        uint32_t addr) {
    asm volatile("ldmatrix.sync.aligned.m8n8.x4.shared.b16 {%0,%1,%2,%3}, [%4];"
                 : "=r"(r0), "=r"(r1), "=r"(r2), "=r"(r3) : "r"(addr));
}
__device__ __forceinline__ void ldsm_x2(uint32_t& r0, uint32_t& r1, uint32_t addr) {
    asm volatile("ldmatrix.sync.aligned.m8n8.x2.shared.b16 {%0,%1}, [%2];"
                 : "=r"(r0), "=r"(r1) : "r"(addr));
}
__device__ __forceinline__ void ldsm_x4t(uint32_t& r0, uint32_t& r1, uint32_t& r2, uint32_t& r3,
                                         uint32_t addr) {
    asm volatile("ldmatrix.sync.aligned.m8n8.x4.trans.shared.b16 {%0,%1,%2,%3}, [%4];"
                 : "=r"(r0), "=r"(r1), "=r"(r2), "=r"(r3) : "r"(addr));
}

// bf16 mma (attention)
__device__ __forceinline__ void mma_16816(float* c, const uint32_t* a, const uint32_t* b) {
    asm volatile(
        "mma.sync.aligned.m16n8k16.row.col.f32.bf16.bf16.f32 "
        "{%0,%1,%2,%3}, {%4,%5,%6,%7}, {%8,%9}, {%0,%1,%2,%3};"
        : "+f"(c[0]), "+f"(c[1]), "+f"(c[2]), "+f"(c[3])
        : "r"(a[0]), "r"(a[1]), "r"(a[2]), "r"(a[3]), "r"(b[0]), "r"(b[1]));
}

// tf32 mma (GEMMs)
__device__ __forceinline__ void mma_tf32(float* c, const uint32_t* a, const uint32_t* b) {
    asm volatile(
        "mma.sync.aligned.m16n8k8.row.col.f32.tf32.tf32.f32 "
        "{%0,%1,%2,%3}, {%4,%5,%6,%7}, {%8,%9}, {%0,%1,%2,%3};"
        : "+f"(c[0]), "+f"(c[1]), "+f"(c[2]), "+f"(c[3])
        : "r"(a[0]), "r"(a[1]), "r"(a[2]), "r"(a[3]), "r"(b[0]), "r"(b[1]));
}

__device__ __forceinline__ uint32_t pack_bf16x2(float a, float b) {
    __nv_bfloat162 t = __floats2bfloat162_rn(a, b);   // low = a
    return *(uint32_t*)&t;
}

__device__ __forceinline__ float tf32r(float x) {
    uint32_t u;
    asm("cvt.rna.tf32.f32 %0, %1;" : "=r"(u) : "f"(x));
    return __uint_as_float(u);
}

// ---------------------------------------------------------------------------
// Round fp32 -> tf32 (rna), stored as fp32
// ---------------------------------------------------------------------------
__global__ __launch_bounds__(256) void round_kernel(
    const float* __restrict__ x, float* __restrict__ y, int n4)
{
    int i = blockIdx.x * blockDim.x + threadIdx.x;
    if (i >= n4) return;
    float4 v = ((const float4*)x)[i];
    ((float4*)y)[i] = make_float4(tf32r(v.x), tf32r(v.y), tf32r(v.z), tf32r(v.w));
}

// ---------------------------------------------------------------------------
// tf32 single-pass GEMM:  C[M,N] = A[M,K] * B[N,K]^T   (fp32 tf32-rounded in)
// CTA 128x128, 8 warps (2M x 4N), 3-stage cp.async, K-chunk 32 fp32 (128B rows).
// BF16OUT: write hi/lo bf16 split instead of fp32.
// ---------------------------------------------------------------------------
#define STAGES   3
#define STAGE_BY 32768          // 16KB A + 16KB B

template<bool BF16OUT>
__global__ __launch_bounds__(256, 2) void gemm_tf32_kernel(
    const float* __restrict__ A, const float* __restrict__ B,
    float* __restrict__ C, __nv_bfloat16* __restrict__ Chi, __nv_bfloat16* __restrict__ Clo,
    int M, int N, int K)
{
    extern __shared__ char smem[];
    const uint32_t sbase = smem_u32(smem);
    const int tid  = threadIdx.x;
    const int wid  = tid >> 5;
    const int lane = tid & 31;
    const int warpM = wid & 1;
    const int warpN = wid >> 1;
    const int bm = blockIdx.y * 128;
    const int bn = blockIdx.x * 128;

    const int nstages = K >> 5;      // 32-fp32 K chunks

    float acc[4][4][4];
#pragma unroll
    for (int i = 0; i < 4; i++)
#pragma unroll
        for (int j = 0; j < 4; j++)
#pragma unroll
            for (int k = 0; k < 4; k++) acc[i][j][k] = 0.0f;

    auto issue = [&](int st) {
        const int k0 = st << 5;
        const uint32_t sA = sbase + (st % STAGES) * STAGE_BY;
        const uint32_t sB = sA + 16384;
#pragma unroll
        for (int s = 0; s < 4; s++) {
            int idx = s * 256 + tid;
            int row = idx >> 3, ch = idx & 7;          // 8 x 16B chunks per 128B row
            uint32_t off = SW128(row * 128 + ch * 16);
            cp_async16(sA + off, A + (size_t)(bm + row) * K + k0 + ch * 4);
            cp_async16(sB + off, B + (size_t)(bn + row) * K + k0 + ch * 4);
        }
        CP_COMMIT();
    };

    issue(0);
    issue(1);

    for (int it = 0; it < nstages; it++) {
        CP_WAIT(1);
        __syncthreads();

        const uint32_t sA = sbase + (it % STAGES) * STAGE_BY;
        const uint32_t sB = sA + 16384;

#pragma unroll
        for (int ks = 0; ks < 4; ks++) {               // 4 x k8 per 32-fp32 chunk
            uint32_t a[4][4], b[4][2];
#pragma unroll
            for (int mt = 0; mt < 4; mt++) {
                int row = warpM * 64 + mt * 16 + (lane & 15);
                int byte = ks * 32 + ((lane >> 4) & 1) * 16;
                ldsm_x4(a[mt][0], a[mt][1], a[mt][2], a[mt][3],
                        sA + SW128(row * 128 + byte));
            }
#pragma unroll
            for (int nt = 0; nt < 4; nt++) {
                int row = warpN * 32 + nt * 8 + (lane & 7);
                int byte = ks * 32 + ((lane >> 3) & 1) * 16;
                ldsm_x2(b[nt][0], b[nt][1], sB + SW128(row * 128 + byte));
            }
#pragma unroll
            for (int mt = 0; mt < 4; mt++)
#pragma unroll
                for (int nt = 0; nt < 4; nt++)
                    mma_tf32(acc[mt][nt], a[mt], b[nt]);
        }

        if (it + STAGES - 1 < nstages) issue(it + STAGES - 1);
    }

#pragma unroll
    for (int mt = 0; mt < 4; mt++) {
#pragma unroll
        for (int nt = 0; nt < 4; nt++) {
            int r0 = bm + warpM * 64 + mt * 16 + (lane >> 2);
            int c0 = bn + warpN * 32 + nt * 8 + (lane & 3) * 2;
            if (BF16OUT) {
#pragma unroll
                for (int half = 0; half < 2; half++) {
                    float v0 = acc[mt][nt][half * 2 + 0];
                    float v1 = acc[mt][nt][half * 2 + 1];
                    __nv_bfloat16 h0 = __float2bfloat16(v0), h1 = __float2bfloat16(v1);
                    float l0 = v0 - __bfloat162float(h0), l1 = v1 - __bfloat162float(h1);
                    size_t off = (size_t)(r0 + half * 8) * N + c0;
                    *(uint32_t*)&Chi[off] = ((uint32_t)*(uint16_t*)&h1 << 16) | *(uint16_t*)&h0;
                    __nv_bfloat16 b0 = __float2bfloat16(l0), b1 = __float2bfloat16(l1);
                    *(uint32_t*)&Clo[off] = ((uint32_t)*(uint16_t*)&b1 << 16) | *(uint16_t*)&b0;
                }
            } else {
                *(float2*)&C[(size_t)r0 * N + c0]       = make_float2(acc[mt][nt][0], acc[mt][nt][1]);
                *(float2*)&C[(size_t)(r0 + 8) * N + c0] = make_float2(acc[mt][nt][2], acc[mt][nt][3]);
            }
        }
    }
}

// ---------------------------------------------------------------------------
// Flash attention, causal, mma.sync split-bf16 (unchanged core).
// Epilogue now writes a single fp32 (tf32-rounded) output for the proj GEMM.
// ---------------------------------------------------------------------------
#define AT_QBY    32768                 // Qhi 16K + Qlo 16K
#define AT_STBY   32768                 // Khi/Klo/Vhi/Vlo 8K each
#define AT_SMEM   (AT_QBY + 3 * AT_STBY)  // 128 KB

__global__ __launch_bounds__(256) void attn_mma_kernel(
    const __nv_bfloat16* __restrict__ qh_g, const __nv_bfloat16* __restrict__ ql_g,
    float* __restrict__ y)
{
    extern __shared__ char smem[];
    const uint32_t sbase = smem_u32(smem);
    const int tid  = threadIdx.x;
    const int wid  = tid >> 5;
    const int lane = tid & 31;
    const int qt = blockIdx.x;          // 0..15 (128-row q tiles)
    const int h  = blockIdx.y;
    const int b  = blockIdx.z;
    const int q0 = qt * 128;
    const size_t rowbase = (size_t)b * T_SEQ;

    const uint32_t sQh = sbase;
    const uint32_t sQl = sbase + 16384;

    // ---- issue Q loads (group with stage 0) ----
    {
        const __nv_bfloat16* srch = qh_g + (rowbase + q0) * C3 + h * HS;
        const __nv_bfloat16* srcl = ql_g + (rowbase + q0) * C3 + h * HS;
#pragma unroll
        for (int s = 0; s < 4; s++) {
            int idx = s * 256 + tid;
            int row = idx >> 3, ch = idx & 7;
            uint32_t off = SW128(row * 128 + ch * 16);
            cp_async16(sQh + off, srch + (size_t)row * C3 + ch * 8);
            cp_async16(sQl + off, srcl + (size_t)row * C3 + ch * 8);
        }
    }

    const int nkt = 2 * qt + 2;

    auto issue_kv = [&](int kt) {
        if (kt < nkt) {
            const int key0 = kt * 64;
            const uint32_t st = sbase + AT_QBY + (kt % 3) * AT_STBY;
            const __nv_bfloat16* kh = qh_g + (rowbase + key0) * C3 + C_EMB + h * HS;
            const __nv_bfloat16* kl = ql_g + (rowbase + key0) * C3 + C_EMB + h * HS;
            const __nv_bfloat16* vh = qh_g + (rowbase + key0) * C3 + 2 * C_EMB + h * HS;
            const __nv_bfloat16* vl = ql_g + (rowbase + key0) * C3 + 2 * C_EMB + h * HS;
#pragma unroll
            for (int s = 0; s < 2; s++) {
                int idx = s * 256 + tid;
                int row = idx >> 3, ch = idx & 7;
                uint32_t off = SW128(row * 128 + ch * 16);
                size_t g = (size_t)row * C3 + ch * 8;
                cp_async16(st + off, kh + g);
                cp_async16(st + 8192 + off, kl + g);
                cp_async16(st + 16384 + off, vh + g);
                cp_async16(st + 24576 + off, vl + g);
            }
        }
        CP_COMMIT();
    };

    issue_kv(0);   // group 0 (Q + stage0)
    issue_kv(1);   // group 1

    float O[8][4];
#pragma unroll
    for (int d = 0; d < 8; d++)
#pragma unroll
        for (int e = 0; e < 4; e++) O[d][e] = 0.0f;
    float m_run[2] = {-1e30f, -1e30f};
    float l_run[2] = {0.0f, 0.0f};

    const int warp16 = wid * 16;

    for (int kt = 0; kt < nkt; kt++) {
        CP_WAIT(1);
        __syncthreads();
        issue_kv(kt + 2);

        const int key0 = kt * 64;
        const uint32_t st  = sbase + AT_QBY + (kt % 3) * AT_STBY;
        const uint32_t sKh = st, sKl = st + 8192, sVh = st + 16384, sVl = st + 24576;

        // ---- S = Qh*Kh^T + Ql*Kh^T + Qh*Kl^T ----
        float S[8][4];
#pragma unroll
        for (int n = 0; n < 8; n++)
#pragma unroll
            for (int e = 0; e < 4; e++) S[n][e] = 0.0f;

#pragma unroll
        for (int kc = 0; kc < 4; kc++) {
            uint32_t qh[4], ql[4];
            {
                int row = warp16 + (lane & 15);
                int byte = kc * 32 + ((lane >> 4) & 1) * 16;
                ldsm_x4(qh[0], qh[1], qh[2], qh[3], sQh + SW128(row * 128 + byte));
                ldsm_x4(ql[0], ql[1], ql[2], ql[3], sQl + SW128(row * 128 + byte));
            }
#pragma unroll
            for (int ntp = 0; ntp < 4; ntp++) {
                uint32_t kh[4], kl[4];
                int krow = ntp * 16 + (lane & 7) + ((lane & 16) >> 1);
                int kbyte = kc * 32 + ((lane >> 3) & 1) * 16;
                ldsm_x4(kh[0], kh[1], kh[2], kh[3], sKh + SW128(krow * 128 + kbyte));
                ldsm_x4(kl[0], kl[1], kl[2], kl[3], sKl + SW128(krow * 128 + kbyte));
                mma_16816(S[2 * ntp],     qh, kh);
                mma_16816(S[2 * ntp],     ql, kh);
                mma_16816(S[2 * ntp],     qh, kl);
                mma_16816(S[2 * ntp + 1], qh, kh + 2);
                mma_16816(S[2 * ntp + 1], ql, kh + 2);
                mma_16816(S[2 * ntp + 1], qh, kl + 2);
            }
        }

        // ---- scale + causal mask ----
#pragma unroll
        for (int n = 0; n < 8; n++)
#pragma unroll
            for (int e = 0; e < 4; e++) S[n][e] *= 0.125f;

        if (kt >= 2 * qt) {
            int qrow = q0 + warp16 + (lane >> 2);
#pragma unroll
            for (int n = 0; n < 8; n++) {
                int key = key0 + n * 8 + (lane & 3) * 2;
                if (key     > qrow)     S[n][0] = -1e30f;
                if (key + 1 > qrow)     S[n][1] = -1e30f;
                if (key     > qrow + 8) S[n][2] = -1e30f;
                if (key + 1 > qrow + 8) S[n][3] = -1e30f;
            }
        }

        // ---- online softmax (rows lane>>2 and lane>>2 + 8) ----
        float mx0 = S[0][0], mx1 = S[0][2];
#pragma unroll
        for (int n = 0; n < 8; n++) {
            mx0 = fmaxf(mx0, fmaxf(S[n][0], S[n][1]));
            mx1 = fmaxf(mx1, fmaxf(S[n][2], S[n][3]));
        }
        mx0 = fmaxf(mx0, __shfl_xor_sync(0xffffffffu, mx0, 1));
        mx0 = fmaxf(mx0, __shfl_xor_sync(0xffffffffu, mx0, 2));
        mx1 = fmaxf(mx1, __shfl_xor_sync(0xffffffffu, mx1, 1));
        mx1 = fmaxf(mx1, __shfl_xor_sync(0xffffffffu, mx1, 2));

        float mn0 = fmaxf(m_run[0], mx0);
        float mn1 = fmaxf(m_run[1], mx1);
        float f0 = __expf(m_run[0] - mn0);
        float f1 = __expf(m_run[1] - mn1);
        m_run[0] = mn0; m_run[1] = mn1;

        float rs0 = 0.0f, rs1 = 0.0f;
#pragma unroll
        for (int n = 0; n < 8; n++) {
            S[n][0] = __expf(S[n][0] - mn0);
            S[n][1] = __expf(S[n][1] - mn0);
            S[n][2] = __expf(S[n][2] - mn1);
            S[n][3] = __expf(S[n][3] - mn1);
            rs0 += S[n][0] + S[n][1];
            rs1 += S[n][2] + S[n][3];
        }
        rs0 += __shfl_xor_sync(0xffffffffu, rs0, 1);
        rs0 += __shfl_xor_sync(0xffffffffu, rs0, 2);
        rs1 += __shfl_xor_sync(0xffffffffu, rs1, 1);
        rs1 += __shfl_xor_sync(0xffffffffu, rs1, 2);
        l_run[0] = l_run[0] * f0 + rs0;
        l_run[1] = l_run[1] * f1 + rs1;

#pragma unroll
        for (int d = 0; d < 8; d++) {
            O[d][0] *= f0; O[d][1] *= f0;
            O[d][2] *= f1; O[d][3] *= f1;
        }

        // ---- build P fragments (hi + lo) in registers ----
        // part->(n,e) mapping yields exactly [a0,a1,a2,a3].
        uint32_t ph[4][4], pl[4][4];
#pragma unroll
        for (int kc = 0; kc < 4; kc++) {
#pragma unroll
            for (int part = 0; part < 4; part++) {
                int n = 2 * kc + (part >> 1);
                int e = (part & 1) * 2;
                float v0 = S[n][e], v1 = S[n][e + 1];
                __nv_bfloat16 h0 = __float2bfloat16(v0), h1 = __float2bfloat16(v1);
                ph[kc][part] = ((uint32_t)*(uint16_t*)&h1 << 16) | *(uint16_t*)&h0;
                pl[kc][part] = pack_bf16x2(v0 - __bfloat162float(h0), v1 - __bfloat162float(h1));
            }
        }

        // ---- O += Ph*Vh + Pl*Vh + Ph*Vl ----
#pragma unroll
        for (int dt = 0; dt < 8; dt++) {
            uint32_t vh[8], vl[8];
            ldsm_x4t(vh[0], vh[1], vh[2], vh[3], sVh + SW128(lane * 128 + dt * 16));
            ldsm_x4t(vh[4], vh[5], vh[6], vh[7], sVh + SW128((32 + lane) * 128 + dt * 16));
            ldsm_x4t(vl[0], vl[1], vl[2], vl[3], sVl + SW128(lane * 128 + dt * 16));
            ldsm_x4t(vl[4], vl[5], vl[6], vl[7], sVl + SW128((32 + lane) * 128 + dt * 16));
#pragma unroll
            for (int kc = 0; kc < 4; kc++) {
                mma_16816(O[dt], ph[kc], vh + 2 * kc);
                mma_16816(O[dt], pl[kc], vh + 2 * kc);
                mma_16816(O[dt], ph[kc], vl + 2 * kc);
            }
        }
        __syncthreads();
    }

    // ---- epilogue: fp32 (tf32-rounded) O / l ----
    float inv0 = 1.0f / l_run[0];
    float inv1 = 1.0f / l_run[1];
    int r0 = q0 + warp16 + (lane >> 2);
#pragma unroll
    for (int dt = 0; dt < 8; dt++) {
        int col = h * HS + dt * 8 + (lane & 3) * 2;
        size_t o0 = (rowbase + r0) * C_EMB + col;
        size_t o1 = (rowbase + r0 + 8) * C_EMB + col;
        *(float2*)&y[o0] = make_float2(tf32r(O[dt][0] * inv0), tf32r(O[dt][1] * inv0));
        *(float2*)&y[o1] = make_float2(tf32r(O[dt][2] * inv1), tf32r(O[dt][3] * inv1));
    }
}

// ---------------------------------------------------------------------------
// Launch
// ---------------------------------------------------------------------------
extern "C" void kernel_launch(void* const* d_in, const int* in_sizes, int n_in,
                              void* d_out, int out_size)
{
    const float* x      = (const float*)d_in[0];
    const float* w_attn = (const float*)d_in[1];
    const float* w_proj = (const float*)d_in[2];
    float* out = (float*)d_out;

    float *xt, *wat, *wpt, *att;
    __nv_bfloat16 *qkvhi, *qkvlo;
    cudaGetSymbolAddress((void**)&xt, g_xt);
    cudaGetSymbolAddress((void**)&wat, g_wat);
    cudaGetSymbolAddress((void**)&wpt, g_wpt);
    cudaGetSymbolAddress((void**)&qkvhi, g_qkvhi);
    cudaGetSymbolAddress((void**)&qkvlo, g_qkvlo);
    cudaGetSymbolAddress((void**)&att, g_att);

    const int smem_gemm = STAGES * STAGE_BY;   // 96 KB
    cudaFuncSetAttribute(gemm_tf32_kernel<true>,  cudaFuncAttributeMaxDynamicSharedMemorySize, smem_gemm);
    cudaFuncSetAttribute(gemm_tf32_kernel<false>, cudaFuncAttributeMaxDynamicSharedMemorySize, smem_gemm);
    cudaFuncSetAttribute(attn_mma_kernel, cudaFuncAttributeMaxDynamicSharedMemorySize, AT_SMEM);

    // tf32 rounding of inputs
    {
        int n4 = MROWS * C_EMB / 4;
        round_kernel<<<(n4 + 255) / 256, 256>>>(x, xt, n4);
        int n4w = C3 * C_EMB / 4;
        round_kernel<<<(n4w + 255) / 256, 256>>>(w_attn, wat, n4w);
        int n4p = C_EMB * C_EMB / 4;
        round_kernel<<<(n4p + 255) / 256, 256>>>(w_proj, wpt, n4p);
    }

    // 1) qkv = x @ w_attn^T (tf32, 1 pass) -> hi/lo bf16
    {
        dim3 grid(C3 / 128, MROWS / 128);
        gemm_tf32_kernel<true><<<grid, 256, smem_gemm>>>(
            xt, wat, nullptr, qkvhi, qkvlo, MROWS, C3, C_EMB);
    }

    // 2) flash attention (split bf16) -> fp32 tf32-rounded att
    {
        dim3 grid(T_SEQ / 128, NH, B_SZ);
        attn_mma_kernel<<<grid, 256, AT_SMEM>>>(qkvhi, qkvlo, att);
    }

    // 3) out = att @ w_proj^T (tf32, 1 pass, fp32 out)
    {
        dim3 grid(C_EMB / 128, MROWS / 128);
        gemm_tf32_kernel<false><<<grid, 256, smem_gemm>>>(
            att, wpt, out, nullptr, nullptr, MROWS, C_EMB, C_EMB);
    }
}